// round 1
// baseline (speedup 1.0000x reference)
#include <cuda_runtime.h>

#define NROWS 65536
#define D 64
#define K 1024
#define TILE_K 128
#define BLOCK 128

// Scratch (no allocations allowed): per-embedding ||e||^2 and loss accumulator.
__device__ float  g_ee[K];
__device__ double g_acc;

__global__ void vq_init_kernel() {
    g_acc = 0.0;
}

__global__ void vq_ee_kernel(const float* __restrict__ emb) {
    int k = blockIdx.x * blockDim.x + threadIdx.x;
    if (k < K) {
        const float* e = emb + k * D;
        float s = 0.f;
        #pragma unroll
        for (int i = 0; i < D; ++i) s += e[i] * e[i];
        g_ee[k] = s;
    }
}

__global__ __launch_bounds__(BLOCK)
void vq_main_kernel(const float* __restrict__ z,
                    const float* __restrict__ emb,
                    float* __restrict__ out) {
    __shared__ float4 s_emb[TILE_K * (D / 4)];   // 32 KB tile of codebook
    __shared__ float  s_ee[TILE_K];
    __shared__ double s_red[BLOCK / 32];

    const int tid = threadIdx.x;
    const int row = blockIdx.x * BLOCK + tid;    // one z-row per thread

    // Load z row into registers (16 x float4 = 64 floats).
    float4 zr[16];
    const float4* zp = reinterpret_cast<const float4*>(z) + (size_t)row * 16;
    #pragma unroll
    for (int j = 0; j < 16; ++j) zr[j] = zp[j];

    // ||z||^2, sequential fp32 order (mirrors reference formula).
    float zz = 0.f;
    #pragma unroll
    for (int j = 0; j < 16; ++j) {
        zz += zr[j].x * zr[j].x;
        zz += zr[j].y * zr[j].y;
        zz += zr[j].z * zr[j].z;
        zz += zr[j].w * zr[j].w;
    }

    float dmin = 3.4e38f;
    int   best = 0;

    for (int t = 0; t < K / TILE_K; ++t) {
        __syncthreads();
        // Cooperative tile load: 128 emb rows * 16 float4 = 2048 float4.
        const float4* ep = reinterpret_cast<const float4*>(emb)
                           + (size_t)t * TILE_K * (D / 4);
        #pragma unroll
        for (int j = 0; j < 16; ++j)
            s_emb[j * BLOCK + tid] = ep[j * BLOCK + tid];
        s_ee[tid] = g_ee[t * TILE_K + tid];
        __syncthreads();

        for (int kk = 0; kk < TILE_K; ++kk) {
            const float4* e = &s_emb[kk * (D / 4)];
            float ze = 0.f;
            #pragma unroll
            for (int j = 0; j < 16; ++j) {
                float4 ev = e[j];              // warp-broadcast LDS, conflict-free
                ze += zr[j].x * ev.x;
                ze += zr[j].y * ev.y;
                ze += zr[j].z * ev.z;
                ze += zr[j].w * ev.w;
            }
            // distance = ||z||^2 - 2 z.e + ||e||^2  (same combine order as ref)
            float d = (zz - 2.0f * ze) + s_ee[kk];
            if (d < dmin) { dmin = d; best = t * TILE_K + kk; }  // first-min
        }
    }

    // Epilogue: write quantized row, accumulate (q - z)^2 in double.
    double lacc = 0.0;
    const float4* eb = reinterpret_cast<const float4*>(emb) + (size_t)best * 16;
    float4* op = reinterpret_cast<float4*>(out) + (size_t)row * 16;
    #pragma unroll
    for (int j = 0; j < 16; ++j) {
        float4 q = eb[j];
        op[j] = q;
        float dx = q.x - zr[j].x;
        float dy = q.y - zr[j].y;
        float dz = q.z - zr[j].z;
        float dw = q.w - zr[j].w;
        lacc += (double)dx * dx + (double)dy * dy
              + (double)dz * dz + (double)dw * dw;
    }

    // Warp + block reduce, single atomicAdd per block.
    #pragma unroll
    for (int off = 16; off; off >>= 1)
        lacc += __shfl_down_sync(0xffffffffu, lacc, off);
    int lane = tid & 31, w = tid >> 5;
    if (lane == 0) s_red[w] = lacc;
    __syncthreads();
    if (tid == 0) {
        double b = 0.0;
        #pragma unroll
        for (int i = 0; i < BLOCK / 32; ++i) b += s_red[i];
        atomicAdd(&g_acc, b);
    }
}

__global__ void vq_fin_kernel(float* __restrict__ out, int out_size) {
    if (out_size > NROWS * D) {
        // loss = (beta + 1) * mean((q - z)^2) = 1.25 * sum / (N*D)
        out[NROWS * D] = (float)(1.25 * g_acc / (double)((long long)NROWS * D));
    }
}

extern "C" void kernel_launch(void* const* d_in, const int* in_sizes, int n_in,
                              void* d_out, int out_size) {
    // Identify inputs by element count (z = 4194304, emb = 65536).
    const float* z   = (const float*)d_in[0];
    const float* emb = (const float*)d_in[1];
    if (n_in >= 2 && in_sizes[0] == K * D && in_sizes[1] == NROWS * D) {
        z   = (const float*)d_in[1];
        emb = (const float*)d_in[0];
    }
    float* out = (float*)d_out;

    vq_init_kernel<<<1, 1>>>();
    vq_ee_kernel<<<(K + 127) / 128, 128>>>(emb);
    vq_main_kernel<<<NROWS / BLOCK, BLOCK>>>(z, emb, out);
    vq_fin_kernel<<<1, 1>>>(out, out_size);
}

// round 2
// speedup vs baseline: 1.0298x; 1.0298x over previous
#include <cuda_runtime.h>

#define NROWS 65536
#define D 64
#define K 1024
#define TILE_K 128
#define BLOCK 128

// Scratch (no allocations allowed): per-embedding ||e||^2 and loss accumulator.
__device__ float  g_ee[K];
__device__ double g_acc;

// ---- packed f32x2 helpers (Blackwell FFMA2 path, PTX-only) ----
__device__ __forceinline__ unsigned long long fma2(unsigned long long a,
                                                   unsigned long long b,
                                                   unsigned long long c) {
    unsigned long long d;
    asm("fma.rn.f32x2 %0, %1, %2, %3;" : "=l"(d) : "l"(a), "l"(b), "l"(c));
    return d;
}
__device__ __forceinline__ unsigned long long add2(unsigned long long a,
                                                   unsigned long long b) {
    unsigned long long d;
    asm("add.rn.f32x2 %0, %1, %2;" : "=l"(d) : "l"(a), "l"(b));
    return d;
}
__device__ __forceinline__ void unpack2(unsigned long long p, float& lo, float& hi) {
    asm("mov.b64 {%0, %1}, %2;" : "=f"(lo), "=f"(hi) : "l"(p));
}

__global__ void vq_init_kernel() {
    g_acc = 0.0;
}

__global__ void vq_ee_kernel(const float* __restrict__ emb) {
    int k = blockIdx.x * blockDim.x + threadIdx.x;
    if (k < K) {
        const float* e = emb + k * D;
        float s = 0.f;
        #pragma unroll
        for (int i = 0; i < D; ++i) s += e[i] * e[i];
        g_ee[k] = s;
    }
}

__global__ __launch_bounds__(BLOCK)
void vq_main_kernel(const float* __restrict__ z,
                    const float* __restrict__ emb,
                    float* __restrict__ out) {
    // Codebook tile: 128 rows x 64 floats = 128 x 16 ulonglong2 = 32 KB.
    __shared__ ulonglong2 s_emb[TILE_K * 16];
    __shared__ float      s_ee[TILE_K];
    __shared__ double     s_red[BLOCK / 32];

    const int tid = threadIdx.x;
    const int row = blockIdx.x * BLOCK + tid;     // one z-row per thread

    // Load z row as 16 x ulonglong2 (= 32 packed f32 pairs).
    ulonglong2 zr[16];
    const ulonglong2* zp = reinterpret_cast<const ulonglong2*>(z) + (size_t)row * 16;
    #pragma unroll
    for (int j = 0; j < 16; ++j) zr[j] = zp[j];

    // ||z||^2 via packed FMAs (4 interleaved accumulators).
    float zz;
    {
        unsigned long long a0 = 0ull, a1 = 0ull, a2 = 0ull, a3 = 0ull;
        #pragma unroll
        for (int j = 0; j < 16; j += 2) {
            a0 = fma2(zr[j].x,     zr[j].x,     a0);
            a1 = fma2(zr[j].y,     zr[j].y,     a1);
            a2 = fma2(zr[j + 1].x, zr[j + 1].x, a2);
            a3 = fma2(zr[j + 1].y, zr[j + 1].y, a3);
        }
        unsigned long long s = add2(add2(a0, a1), add2(a2, a3));
        float lo, hi; unpack2(s, lo, hi);
        zz = lo + hi;
    }

    float dmin = 3.4e38f;
    int   best = 0;

    for (int t = 0; t < K / TILE_K; ++t) {
        __syncthreads();
        // Cooperative tile load: 128 rows * 16 ulonglong2 = 2048 x 16B.
        const ulonglong2* ep = reinterpret_cast<const ulonglong2*>(emb)
                               + (size_t)t * TILE_K * 16;
        #pragma unroll
        for (int j = 0; j < 16; ++j)
            s_emb[j * BLOCK + tid] = ep[j * BLOCK + tid];
        s_ee[tid] = g_ee[t * TILE_K + tid];
        __syncthreads();

        for (int kk = 0; kk < TILE_K; ++kk) {
            const ulonglong2* e = &s_emb[kk * 16];
            unsigned long long a0 = 0ull, a1 = 0ull, a2 = 0ull, a3 = 0ull;
            #pragma unroll
            for (int j = 0; j < 16; j += 2) {
                ulonglong2 e0 = e[j];          // LDS.128 broadcast, conflict-free
                ulonglong2 e1 = e[j + 1];
                a0 = fma2(zr[j].x,     e0.x, a0);
                a1 = fma2(zr[j].y,     e0.y, a1);
                a2 = fma2(zr[j + 1].x, e1.x, a2);
                a3 = fma2(zr[j + 1].y, e1.y, a3);
            }
            unsigned long long s = add2(add2(a0, a1), add2(a2, a3));
            float lo, hi; unpack2(s, lo, hi);
            float ze = lo + hi;
            // distance = ||z||^2 - 2 z.e + ||e||^2
            float d = (zz - 2.0f * ze) + s_ee[kk];
            if (d < dmin) { dmin = d; best = t * TILE_K + kk; }  // first-min
        }
    }

    // Epilogue: write quantized row, accumulate (q - z)^2 in double.
    double lacc = 0.0;
    const float4* eb = reinterpret_cast<const float4*>(emb) + (size_t)best * 16;
    float4* op = reinterpret_cast<float4*>(out) + (size_t)row * 16;
    #pragma unroll
    for (int j = 0; j < 16; ++j) {
        float4 q = eb[j];
        op[j] = q;
        float zx, zy, zzv, zw;
        unpack2(zr[j].x, zx, zy);
        unpack2(zr[j].y, zzv, zw);
        float dx = q.x - zx;
        float dy = q.y - zy;
        float dz = q.z - zzv;
        float dw = q.w - zw;
        lacc += (double)dx * dx + (double)dy * dy
              + (double)dz * dz + (double)dw * dw;
    }

    // Warp + block reduce, single atomicAdd per block.
    #pragma unroll
    for (int off = 16; off; off >>= 1)
        lacc += __shfl_down_sync(0xffffffffu, lacc, off);
    int lane = tid & 31, w = tid >> 5;
    if (lane == 0) s_red[w] = lacc;
    __syncthreads();
    if (tid == 0) {
        double b = 0.0;
        #pragma unroll
        for (int i = 0; i < BLOCK / 32; ++i) b += s_red[i];
        atomicAdd(&g_acc, b);
    }
}

__global__ void vq_fin_kernel(float* __restrict__ out, int out_size) {
    if (out_size > NROWS * D) {
        // loss = (beta + 1) * mean((q - z)^2) = 1.25 * sum / (N*D)
        out[NROWS * D] = (float)(1.25 * g_acc / (double)((long long)NROWS * D));
    }
}

extern "C" void kernel_launch(void* const* d_in, const int* in_sizes, int n_in,
                              void* d_out, int out_size) {
    // Identify inputs by element count (z = 4194304, emb = 65536).
    const float* z   = (const float*)d_in[0];
    const float* emb = (const float*)d_in[1];
    if (n_in >= 2 && in_sizes[0] == K * D && in_sizes[1] == NROWS * D) {
        z   = (const float*)d_in[1];
        emb = (const float*)d_in[0];
    }
    float* out = (float*)d_out;

    vq_init_kernel<<<1, 1>>>();
    vq_ee_kernel<<<(K + 127) / 128, 128>>>(emb);
    vq_main_kernel<<<NROWS / BLOCK, BLOCK>>>(z, emb, out);
    vq_fin_kernel<<<1, 1>>>(out, out_size);
}

// round 3
// speedup vs baseline: 1.3196x; 1.2815x over previous
#include <cuda_runtime.h>
#include <cuda_bf16.h>
#include <mma.h>
using namespace nvcuda;

#define NROWS 65536
#define D 64
#define K 1024
#define BLOCK 128
#define CH 64              // codebook entries per MMA chunk
#define NCH (K / CH)       // 16
#define TAU 2e-4f
#define RW 8               // rescored rows per block (8 warps)

// Static scratch (no allocations allowed).
__device__ __nv_bfloat16 g_emb_bf16[K * D];
__device__ float  g_ee[K];
__device__ double g_acc;
__device__ int    g_rescore_n;
__device__ int    g_rescore_rows[NROWS];

// Dynamic smem layout for main kernel.
#define SZ_Z   (128 * 72)                 // bf16
#define SZ_E   (64 * 72)                  // bf16
#define SZ_S   (64 * 136)                 // f32, col-major ld=136
#define SMEM_MAIN ((SZ_Z + SZ_E) * 2 + (SZ_S + K) * 4 + 4 * 8)

__global__ void vq_pre_kernel(const float* __restrict__ emb) {
    int k = blockIdx.x * blockDim.x + threadIdx.x;
    if (k == 0) { g_acc = 0.0; g_rescore_n = 0; }
    if (k < K) {
        const float4* e = (const float4*)(emb + k * D);
        float s = 0.f;
        #pragma unroll
        for (int j = 0; j < 16; ++j) {
            float4 v = e[j];
            s += v.x * v.x; s += v.y * v.y; s += v.z * v.z; s += v.w * v.w;
            __nv_bfloat162 p0, p1;
            p0.x = __float2bfloat16(v.x); p0.y = __float2bfloat16(v.y);
            p1.x = __float2bfloat16(v.z); p1.y = __float2bfloat16(v.w);
            *(__nv_bfloat162*)(g_emb_bf16 + k * D + j * 4)     = p0;
            *(__nv_bfloat162*)(g_emb_bf16 + k * D + j * 4 + 2) = p1;
        }
        g_ee[k] = s;
    }
}

__global__ __launch_bounds__(BLOCK)
void vq_main_kernel(const float* __restrict__ z,
                    const float* __restrict__ emb,
                    float* __restrict__ out) {
    extern __shared__ char smem_raw[];
    __nv_bfloat16* s_z  = (__nv_bfloat16*)smem_raw;      // [128][72]
    __nv_bfloat16* s_e  = s_z + SZ_Z;                    // [64][72]
    float*  s_S   = (float*)(s_e + SZ_E);                // col-major [64 cols][ld=136]
    float*  s_ee  = s_S + SZ_S;                          // [1024]
    double* s_red = (double*)(s_ee + K);                 // [4]

    const int tid  = threadIdx.x;
    const int warp = tid >> 5;
    const int row  = blockIdx.x * BLOCK + tid;           // one z-row per thread

    // Convert this thread's z row to bf16 into smem.
    const float4* zp = (const float4*)z + (size_t)row * 16;
    #pragma unroll
    for (int j = 0; j < 16; ++j) {
        float4 v = zp[j];
        __nv_bfloat162 p0, p1;
        p0.x = __float2bfloat16(v.x); p0.y = __float2bfloat16(v.y);
        p1.x = __float2bfloat16(v.z); p1.y = __float2bfloat16(v.w);
        *(__nv_bfloat162*)(s_z + tid * 72 + j * 4)     = p0;
        *(__nv_bfloat162*)(s_z + tid * 72 + j * 4 + 2) = p1;
    }
    #pragma unroll
    for (int i = 0; i < K / BLOCK; ++i)
        s_ee[i * BLOCK + tid] = g_ee[i * BLOCK + tid];

    float min1 = 3.4e38f, min2 = 3.4e38f;
    int   idx1 = 0;

    wmma::fragment<wmma::accumulator, 16, 16, 16, float> acc[2][4];
    wmma::fragment<wmma::matrix_a, 16, 16, 16, __nv_bfloat16, wmma::row_major> af;
    wmma::fragment<wmma::matrix_b, 16, 16, 16, __nv_bfloat16, wmma::col_major> bfr[4];

    for (int ch = 0; ch < NCH; ++ch) {
        __syncthreads();
        // Load 64 codebook entries (bf16) into s_e: 2 threads per entry, 64B each.
        {
            int e = tid >> 1, h = tid & 1;
            const float4* src = (const float4*)(g_emb_bf16 + (ch * CH + e) * D) + h * 4;
            float4* dst = (float4*)(s_e + e * 72) + h * 4;   // e*144B + h*64B: 16B aligned
            #pragma unroll
            for (int i = 0; i < 4; ++i) dst[i] = src[i];
        }
        __syncthreads();

        #pragma unroll
        for (int i = 0; i < 2; ++i)
            #pragma unroll
            for (int j = 0; j < 4; ++j)
                wmma::fill_fragment(acc[i][j], 0.f);

        #pragma unroll
        for (int kt = 0; kt < 4; ++kt) {
            #pragma unroll
            for (int j = 0; j < 4; ++j)
                wmma::load_matrix_sync(bfr[j], s_e + (j * 16) * 72 + kt * 16, 72);
            #pragma unroll
            for (int i = 0; i < 2; ++i) {
                wmma::load_matrix_sync(af, s_z + (warp * 32 + i * 16) * 72 + kt * 16, 72);
                #pragma unroll
                for (int j = 0; j < 4; ++j)
                    wmma::mma_sync(acc[i][j], af, bfr[j], acc[i][j]);
            }
        }

        // Store S col-major (ld=136 avoids bank conflicts on the row scan).
        #pragma unroll
        for (int i = 0; i < 2; ++i)
            #pragma unroll
            for (int j = 0; j < 4; ++j)
                wmma::store_matrix_sync(s_S + (j * 16) * 136 + warp * 32 + i * 16,
                                        acc[i][j], 136, wmma::mem_col_major);
        __syncthreads();

        // Scan: thread t owns row t; entries are columns. d' = ||e||^2 - 2 z.e
        #pragma unroll 8
        for (int j = 0; j < CH; ++j) {
            float s = s_S[j * 136 + tid];
            int   e = ch * CH + j;
            float d = s_ee[e] - 2.f * s;
            if (d < min1)      { min2 = min1; min1 = d; idx1 = e; }
            else if (d < min2) { min2 = d; }
        }
    }

    // Finalize or defer to exact rescore.
    double lacc = 0.0;
    if (min2 - min1 < TAU) {
        int pos = atomicAdd(&g_rescore_n, 1);
        g_rescore_rows[pos] = row;
    } else {
        const float4* eb = (const float4*)emb + (size_t)idx1 * 16;
        float4* op = (float4*)out + (size_t)row * 16;
        #pragma unroll
        for (int j = 0; j < 16; ++j) {
            float4 q = eb[j];
            float4 zv = zp[j];
            op[j] = q;
            float dx = q.x - zv.x, dy = q.y - zv.y;
            float dz = q.z - zv.z, dw = q.w - zv.w;
            lacc += (double)dx * dx + (double)dy * dy
                  + (double)dz * dz + (double)dw * dw;
        }
    }
    #pragma unroll
    for (int off = 16; off; off >>= 1)
        lacc += __shfl_down_sync(0xffffffffu, lacc, off);
    if ((tid & 31) == 0) s_red[warp] = lacc;
    __syncthreads();
    if (tid == 0) {
        double b = s_red[0] + s_red[1] + s_red[2] + s_red[3];
        atomicAdd(&g_acc, b);
    }
}

// Exact fp32 full rescan for near-tie rows (identical arithmetic order to the
// R1 kernel, which matched the reference). One warp per row.
__global__ __launch_bounds__(256)
void vq_rescore_kernel(const float* __restrict__ z,
                       const float* __restrict__ emb,
                       float* __restrict__ out) {
    __shared__ float s_emb[128 * 69];    // fp32 codebook tile, ld=69 (conflict-free)
    __shared__ float s_zrow[RW * 64];
    __shared__ int   s_rows[RW];

    int nre  = g_rescore_n;
    int base = blockIdx.x * RW;
    if (base >= nre) return;

    int tid = threadIdx.x;
    int w = tid >> 5, l = tid & 31;

    if (tid < RW)
        s_rows[tid] = (base + tid < nre) ? g_rescore_rows[base + tid] : -1;
    __syncthreads();

    if (tid < RW * 16) {
        int rw = tid >> 4, j = tid & 15;
        int r = s_rows[rw];
        if (r >= 0)
            *(float4*)(s_zrow + rw * 64 + j * 4) = ((const float4*)z)[(size_t)r * 16 + j];
    }
    __syncthreads();

    int myrow = s_rows[w];

    float zz = 0.f;
    if (myrow >= 0)
        for (int i = 0; i < 64; ++i) { float v = s_zrow[w * 64 + i]; zz += v * v; }

    float dmin = 3.4e38f;
    int   best = 0;

    for (int t = 0; t < K / 128; ++t) {
        __syncthreads();
        for (int f = tid; f < 128 * 16; f += 256) {
            int e = f >> 4, j = f & 15;
            float4 v = ((const float4*)emb)[(size_t)(t * 128 + e) * 16 + j];
            float* dst = s_emb + e * 69 + j * 4;
            dst[0] = v.x; dst[1] = v.y; dst[2] = v.z; dst[3] = v.w;
        }
        __syncthreads();
        if (myrow >= 0) {
            #pragma unroll
            for (int s = 0; s < 4; ++s) {
                int el = s * 32 + l;
                const float* e = s_emb + el * 69;
                float ze = 0.f;
                for (int i = 0; i < 64; ++i) ze += s_zrow[w * 64 + i] * e[i];
                int ge = t * 128 + el;
                float d = (zz - 2.0f * ze) + g_ee[ge];
                if (d < dmin) { dmin = d; best = ge; }
            }
        }
    }

    // Warp argmin merge; ties -> lowest index (matches jnp.argmin).
    #pragma unroll
    for (int off = 16; off; off >>= 1) {
        float od = __shfl_down_sync(0xffffffffu, dmin, off);
        int   oi = __shfl_down_sync(0xffffffffu, best, off);
        if (od < dmin || (od == dmin && oi < best)) { dmin = od; best = oi; }
    }

    if (myrow >= 0 && l == 0) {
        const float4* eb = (const float4*)emb + (size_t)best * 16;
        float4* op = (float4*)out + (size_t)myrow * 16;
        double lacc = 0.0;
        for (int j = 0; j < 16; ++j) {
            float4 q = eb[j];
            float zx = s_zrow[w * 64 + j * 4 + 0];
            float zy = s_zrow[w * 64 + j * 4 + 1];
            float zzv = s_zrow[w * 64 + j * 4 + 2];
            float zw = s_zrow[w * 64 + j * 4 + 3];
            op[j] = q;
            float dx = q.x - zx, dy = q.y - zy, dz = q.z - zzv, dw = q.w - zw;
            lacc += (double)dx * dx + (double)dy * dy
                  + (double)dz * dz + (double)dw * dw;
        }
        atomicAdd(&g_acc, lacc);
    }
}

__global__ void vq_fin_kernel(float* __restrict__ out, int out_size) {
    if (out_size > NROWS * D) {
        out[NROWS * D] = (float)(1.25 * g_acc / (double)((long long)NROWS * D));
    }
}

extern "C" void kernel_launch(void* const* d_in, const int* in_sizes, int n_in,
                              void* d_out, int out_size) {
    const float* z   = (const float*)d_in[0];
    const float* emb = (const float*)d_in[1];
    if (n_in >= 2 && in_sizes[0] == K * D && in_sizes[1] == NROWS * D) {
        z   = (const float*)d_in[1];
        emb = (const float*)d_in[0];
    }
    float* out = (float*)d_out;

    cudaFuncSetAttribute(vq_main_kernel,
                         cudaFuncAttributeMaxDynamicSharedMemorySize, SMEM_MAIN);

    vq_pre_kernel<<<8, 128>>>(emb);
    vq_main_kernel<<<NROWS / BLOCK, BLOCK, SMEM_MAIN>>>(z, emb, out);
    vq_rescore_kernel<<<NROWS / RW, 256>>>(z, emb, out);
    vq_fin_kernel<<<1, 1>>>(out, out_size);
}

// round 5
// speedup vs baseline: 1.5649x; 1.1858x over previous
#include <cuda_runtime.h>
#include <cuda_bf16.h>
#include <cstdint>

#define NROWS 65536
#define D 64
#define K 1024
#define BLOCK 256          // 8 warps; 32 rows/warp; 256 rows/CTA
#define CH 256             // codebook entries per smem chunk
#define NCH (K / CH)       // 4
#define BSTRIDE 72         // padded bf16 row stride: banks = 4g+t (conflict-free)
#define TAU 2e-4f
#define RW 8

// Static scratch (no allocations allowed).
__device__ __nv_bfloat16 g_emb_bf16[K * D];
__device__ float  g_ee[K];
__device__ double g_acc;
__device__ int    g_rescore_n;
__device__ int    g_rescore_rows[NROWS];

__device__ __forceinline__ uint32_t pack_bf16x2(float a, float b) {
    __nv_bfloat162 h = __floats2bfloat162_rn(a, b);
    return *(uint32_t*)&h;
}

__device__ __forceinline__ void mma16816(float& c0, float& c1, float& c2, float& c3,
                                         uint32_t a0, uint32_t a1, uint32_t a2, uint32_t a3,
                                         uint32_t b0, uint32_t b1) {
    asm volatile("mma.sync.aligned.m16n8k16.row.col.f32.bf16.bf16.f32 "
                 "{%0,%1,%2,%3}, {%4,%5,%6,%7}, {%8,%9}, {%0,%1,%2,%3};"
                 : "+f"(c0), "+f"(c1), "+f"(c2), "+f"(c3)
                 : "r"(a0), "r"(a1), "r"(a2), "r"(a3), "r"(b0), "r"(b1));
}

struct MinState { float m1, m2; int idx; };

__device__ __forceinline__ void upd(MinState& s, float d, int e) {
    float mx = fmaxf(s.m1, d);
    bool  lt = d < s.m1;
    s.m1  = fminf(s.m1, d);
    s.idx = lt ? e : s.idx;
    s.m2  = fminf(s.m2, mx);
}

__device__ __forceinline__ void red4(MinState& s) {
    #pragma unroll
    for (int off = 1; off <= 2; off <<= 1) {
        float om1 = __shfl_xor_sync(0xffffffffu, s.m1, off);
        float om2 = __shfl_xor_sync(0xffffffffu, s.m2, off);
        int   oix = __shfl_xor_sync(0xffffffffu, s.idx, off);
        bool take = (om1 < s.m1) || (om1 == s.m1 && oix < s.idx);
        float nm2 = fminf(fminf(s.m2, om2), fmaxf(s.m1, om1));
        s.m1  = fminf(s.m1, om1);
        s.idx = take ? oix : s.idx;
        s.m2  = nm2;
    }
}

__global__ void vq_pre_kernel(const float* __restrict__ emb) {
    int k = blockIdx.x * blockDim.x + threadIdx.x;
    if (k == 0) { g_acc = 0.0; g_rescore_n = 0; }
    if (k < K) {
        const float4* e = (const float4*)(emb + k * D);
        float s = 0.f;
        #pragma unroll
        for (int j = 0; j < 16; ++j) {
            float4 v = e[j];
            s += v.x * v.x; s += v.y * v.y; s += v.z * v.z; s += v.w * v.w;
            uint32_t p0 = pack_bf16x2(v.x, v.y);
            uint32_t p1 = pack_bf16x2(v.z, v.w);
            *(uint32_t*)(g_emb_bf16 + k * D + j * 4)     = p0;
            *(uint32_t*)(g_emb_bf16 + k * D + j * 4 + 2) = p1;
        }
        g_ee[k] = s;
    }
}

__global__ __launch_bounds__(BLOCK)
void vq_main_kernel(const float* __restrict__ z,
                    const float* __restrict__ emb,
                    float* __restrict__ out) {
    __shared__ __nv_bfloat16 s_b[CH * BSTRIDE];    // 36 KB codebook chunk
    __shared__ float  s_ee[K];
    __shared__ float  s_m1[BLOCK], s_m2[BLOCK];
    __shared__ int    s_ix[BLOCK];
    __shared__ double s_red[BLOCK / 32];

    const int tid   = threadIdx.x;
    const int warp  = tid >> 5;
    const int lane  = tid & 31;
    const int g     = lane >> 2;          // group id (0..7)
    const int t     = lane & 3;           // thread-in-group (0..3)
    const int rbase = blockIdx.x * BLOCK; // 256 rows per CTA
    const int wrow  = rbase + warp * 32;  // this warp's first row

    #pragma unroll
    for (int i = 0; i < K / BLOCK; ++i)
        s_ee[i * BLOCK + tid] = g_ee[i * BLOCK + tid];

    // A fragments: z rows in bf16, resident in registers for the whole kernel.
    // tile0 = rows wrow+g, wrow+8+g ; tile1 = +16. a[tile][kstep][0..3]:
    // a0:(row g, k 2t..2t+1)  a1:(row g+8, same)  a2:(row g, k+8)  a3:(row g+8, k+8)
    uint32_t A[2][4][4];
    #pragma unroll
    for (int tl = 0; tl < 2; ++tl) {
        const float* r0 = z + (size_t)(wrow + tl * 16 + g) * D;
        const float* r1 = r0 + 8 * D;
        #pragma unroll
        for (int ks = 0; ks < 4; ++ks) {
            int kb = ks * 16 + 2 * t;
            float2 u0 = *(const float2*)(r0 + kb);
            float2 u1 = *(const float2*)(r1 + kb);
            float2 u2 = *(const float2*)(r0 + kb + 8);
            float2 u3 = *(const float2*)(r1 + kb + 8);
            A[tl][ks][0] = pack_bf16x2(u0.x, u0.y);
            A[tl][ks][1] = pack_bf16x2(u1.x, u1.y);
            A[tl][ks][2] = pack_bf16x2(u2.x, u2.y);
            A[tl][ks][3] = pack_bf16x2(u3.x, u3.y);
        }
    }

    MinState U0 = {3.4e38f, 3.4e38f, 0}, L0 = U0, U1 = U0, L1 = U0;

    for (int ch = 0; ch < NCH; ++ch) {
        __syncthreads();
        // Stage 256 codebook entries (bf16) into padded smem; conflict-free LDS later.
        {
            const uint4* src = (const uint4*)g_emb_bf16 + (size_t)(ch * CH + tid) * 8;
            uint4* dst = (uint4*)(s_b + tid * BSTRIDE);   // 144 B stride, 16B aligned
            #pragma unroll
            for (int i = 0; i < 8; ++i) dst[i] = src[i];
        }
        __syncthreads();

        for (int nt = 0; nt < CH / 8; ++nt) {
            const int nbl = nt * 8;
            const int nb  = ch * CH + nbl;
            float c00 = 0.f, c01 = 0.f, c02 = 0.f, c03 = 0.f;
            float c10 = 0.f, c11 = 0.f, c12 = 0.f, c13 = 0.f;
            const __nv_bfloat16* brow = s_b + (nbl + g) * BSTRIDE + 2 * t;
            #pragma unroll
            for (int ks = 0; ks < 4; ++ks) {
                uint32_t b0 = *(const uint32_t*)(brow + ks * 16);
                uint32_t b1 = *(const uint32_t*)(brow + ks * 16 + 8);
                mma16816(c00, c01, c02, c03,
                         A[0][ks][0], A[0][ks][1], A[0][ks][2], A[0][ks][3], b0, b1);
                mma16816(c10, c11, c12, c13,
                         A[1][ks][0], A[1][ks][1], A[1][ks][2], A[1][ks][3], b0, b1);
            }
            // cols of c0/c1: e0 = nb+2t, e1 = e0+1 (c2/c3: same cols, row+8)
            float2 ee = *(const float2*)(s_ee + nb + 2 * t);
            int e0 = nb + 2 * t, e1 = e0 + 1;
            upd(U0, fmaf(-2.f, c00, ee.x), e0);
            upd(U0, fmaf(-2.f, c01, ee.y), e1);
            upd(L0, fmaf(-2.f, c02, ee.x), e0);
            upd(L0, fmaf(-2.f, c03, ee.y), e1);
            upd(U1, fmaf(-2.f, c10, ee.x), e0);
            upd(U1, fmaf(-2.f, c11, ee.y), e1);
            upd(L1, fmaf(-2.f, c12, ee.x), e0);
            upd(L1, fmaf(-2.f, c13, ee.y), e1);
        }
    }

    // Merge across the 4 lanes sharing each row, then park per-row results.
    red4(U0); red4(L0); red4(U1); red4(L1);
    if (t == 0) {
        int lr = warp * 32 + g;
        s_m1[lr]      = U0.m1; s_m2[lr]      = U0.m2; s_ix[lr]      = U0.idx;
        s_m1[lr + 8]  = L0.m1; s_m2[lr + 8]  = L0.m2; s_ix[lr + 8]  = L0.idx;
        s_m1[lr + 16] = U1.m1; s_m2[lr + 16] = U1.m2; s_ix[lr + 16] = U1.idx;
        s_m1[lr + 24] = L1.m1; s_m2[lr + 24] = L1.m2; s_ix[lr + 24] = L1.idx;
    }
    __syncthreads();

    // Epilogue: one thread per row.
    const int row = rbase + tid;
    float m1 = s_m1[tid], m2 = s_m2[tid];
    int   idx1 = s_ix[tid];
    const float4* zp = (const float4*)z + (size_t)row * 16;

    double lacc = 0.0;
    if (m2 - m1 < TAU) {
        int pos = atomicAdd(&g_rescore_n, 1);
        g_rescore_rows[pos] = row;
    } else {
        const float4* eb = (const float4*)emb + (size_t)idx1 * 16;
        float4* op = (float4*)out + (size_t)row * 16;
        #pragma unroll
        for (int j = 0; j < 16; ++j) {
            float4 q = eb[j];
            float4 zv = zp[j];
            op[j] = q;
            float dx = q.x - zv.x, dy = q.y - zv.y;
            float dz = q.z - zv.z, dw = q.w - zv.w;
            lacc += (double)dx * dx + (double)dy * dy
                  + (double)dz * dz + (double)dw * dw;
        }
    }
    #pragma unroll
    for (int off = 16; off; off >>= 1)
        lacc += __shfl_down_sync(0xffffffffu, lacc, off);
    if (lane == 0) s_red[warp] = lacc;
    __syncthreads();
    if (tid == 0) {
        double b = 0.0;
        #pragma unroll
        for (int i = 0; i < BLOCK / 32; ++i) b += s_red[i];
        atomicAdd(&g_acc, b);
    }
}

// Exact fp32 full rescan for near-tie rows (R1 arithmetic order; matched ref).
__global__ __launch_bounds__(256)
void vq_rescore_kernel(const float* __restrict__ z,
                       const float* __restrict__ emb,
                       float* __restrict__ out) {
    __shared__ float s_emb[128 * 69];
    __shared__ float s_zrow[RW * 64];
    __shared__ int   s_rows[RW];

    int nre  = g_rescore_n;
    int base = blockIdx.x * RW;
    if (base >= nre) return;

    int tid = threadIdx.x;
    int w = tid >> 5, l = tid & 31;

    if (tid < RW)
        s_rows[tid] = (base + tid < nre) ? g_rescore_rows[base + tid] : -1;
    __syncthreads();

    if (tid < RW * 16) {
        int rw = tid >> 4, j = tid & 15;
        int r = s_rows[rw];
        if (r >= 0)
            *(float4*)(s_zrow + rw * 64 + j * 4) = ((const float4*)z)[(size_t)r * 16 + j];
    }
    __syncthreads();

    int myrow = s_rows[w];

    float zz = 0.f;
    if (myrow >= 0)
        for (int i = 0; i < 64; ++i) { float v = s_zrow[w * 64 + i]; zz += v * v; }

    float dmin = 3.4e38f;
    int   best = 0;

    for (int tt = 0; tt < K / 128; ++tt) {
        __syncthreads();
        for (int f = tid; f < 128 * 16; f += 256) {
            int e = f >> 4, j = f & 15;
            float4 v = ((const float4*)emb)[(size_t)(tt * 128 + e) * 16 + j];
            float* dst = s_emb + e * 69 + j * 4;
            dst[0] = v.x; dst[1] = v.y; dst[2] = v.z; dst[3] = v.w;
        }
        __syncthreads();
        if (myrow >= 0) {
            #pragma unroll
            for (int s = 0; s < 4; ++s) {
                int el = s * 32 + l;
                const float* e = s_emb + el * 69;
                float ze = 0.f;
                for (int i = 0; i < 64; ++i) ze += s_zrow[w * 64 + i] * e[i];
                int ge = tt * 128 + el;
                float d = (zz - 2.0f * ze) + g_ee[ge];
                if (d < dmin) { dmin = d; best = ge; }
            }
        }
    }

    #pragma unroll
    for (int off = 16; off; off >>= 1) {
        float od = __shfl_down_sync(0xffffffffu, dmin, off);
        int   oi = __shfl_down_sync(0xffffffffu, best, off);
        if (od < dmin || (od == dmin && oi < best)) { dmin = od; best = oi; }
    }

    if (myrow >= 0 && l == 0) {
        const float4* eb = (const float4*)emb + (size_t)best * 16;
        float4* op = (float4*)out + (size_t)myrow * 16;
        double lacc = 0.0;
        for (int j = 0; j < 16; ++j) {
            float4 q = eb[j];
            float zx = s_zrow[w * 64 + j * 4 + 0];
            float zy = s_zrow[w * 64 + j * 4 + 1];
            float zzv = s_zrow[w * 64 + j * 4 + 2];
            float zw = s_zrow[w * 64 + j * 4 + 3];
            op[j] = q;
            float dx = q.x - zx, dy = q.y - zy, dz = q.z - zzv, dw = q.w - zw;
            lacc += (double)dx * dx + (double)dy * dy
                  + (double)dz * dz + (double)dw * dw;
        }
        atomicAdd(&g_acc, lacc);
    }
}

__global__ void vq_fin_kernel(float* __restrict__ out, int out_size) {
    if (out_size > NROWS * D) {
        out[NROWS * D] = (float)(1.25 * g_acc / (double)((long long)NROWS * D));
    }
}

extern "C" void kernel_launch(void* const* d_in, const int* in_sizes, int n_in,
                              void* d_out, int out_size) {
    const float* z   = (const float*)d_in[0];
    const float* emb = (const float*)d_in[1];
    if (n_in >= 2 && in_sizes[0] == K * D && in_sizes[1] == NROWS * D) {
        z   = (const float*)d_in[1];
        emb = (const float*)d_in[0];
    }
    float* out = (float*)d_out;

    vq_pre_kernel<<<8, 128>>>(emb);
    vq_main_kernel<<<NROWS / BLOCK, BLOCK>>>(z, emb, out);
    vq_rescore_kernel<<<NROWS / RW, 256>>>(z, emb, out);
    vq_fin_kernel<<<1, 1>>>(out, out_size);
}